// round 1
// baseline (speedup 1.0000x reference)
#include <cuda_runtime.h>

// LIF neuron group: T=1000 sequential steps over N=65536 independent neurons.
// Pure HBM streaming: 512 MB read + 256 MB write, zero reuse.
// One thread owns 4 adjacent neurons (float4), state (V, V_th) in registers,
// serial loop over t with unroll-4 to front-batch loads (MLP ~8 per thread).

#define NUM_NEURONS 65536
#define T_STEPS     1000
#define VEC         4
#define NVEC        (NUM_NEURONS / VEC)   // 16384 float4 lanes
#define THREADS     64
#define BLOCKS      (NVEC / THREADS)      // 256 blocks -> all 148 SMs busy

__global__ __launch_bounds__(THREADS)
void lif_kernel(const float4* __restrict__ icur,
                const float4* __restrict__ nz,
                float4* __restrict__ out)
{
    const int idx = blockIdx.x * THREADS + threadIdx.x;   // 0 .. NVEC-1

    const float decay = 0.05f;   // DT/TAU = 1/20
    const float eta   = 0.1f;    // ETA
    const float nstd  = 0.1f;    // NOISE_STD
    const float thmin = 0.5f;
    const float thmax = 2.0f;

    float4 V  = make_float4(0.0f, 0.0f, 0.0f, 0.0f);
    float4 th = make_float4(1.0f, 1.0f, 1.0f, 1.0f);

    const float4* ip = icur + idx;
    const float4* np = nz   + idx;
    float4*       op = out  + idx;

#pragma unroll 4
    for (int t = 0; t < T_STEPS; t++) {
        float4 i4 = __ldcs(ip + (size_t)t * NVEC);
        float4 n4 = __ldcs(np + (size_t)t * NVEC);
        float4 s;

        // Per-component LIF update, op order matching the JAX reference:
        //   I_eff = I + nstd*n            (fma)
        //   V     = V + decay*(I_eff - V) (fma)
        //   spike = V >= th
        //   V     = spike ? 0 : V
        //   th    = clip(th + eta*spike, thmin, thmax)
#define LIF_STEP(c)                                                  \
        {                                                            \
            float ie = fmaf(nstd, n4.c, i4.c);                       \
            float v  = fmaf(decay, ie - V.c, V.c);                   \
            bool  sp = (v >= th.c);                                  \
            s.c  = sp ? 1.0f : 0.0f;                                 \
            V.c  = sp ? 0.0f : v;                                    \
            th.c = fminf(fmaxf(fmaf(eta, s.c, th.c), thmin), thmax); \
        }

        LIF_STEP(x)
        LIF_STEP(y)
        LIF_STEP(z)
        LIF_STEP(w)
#undef LIF_STEP

        __stcs(op + (size_t)t * NVEC, s);
    }
}

extern "C" void kernel_launch(void* const* d_in, const int* in_sizes, int n_in,
                              void* d_out, int out_size)
{
    const float4* icur = (const float4*)d_in[0];   // input_current (T, N) f32
    const float4* nz   = (const float4*)d_in[1];   // noise         (T, N) f32
    float4*       out  = (float4*)d_out;           // spikes        (T, N) f32

    lif_kernel<<<BLOCKS, THREADS>>>(icur, nz, out);
}

// round 2
// speedup vs baseline: 3.8207x; 3.8207x over previous
#include <cuda_runtime.h>

// LIF neuron group, T=1000 serial steps x 65536 neurons.
// Pure HBM stream (512 MB read + 256 MB write, zero reuse).
// R1 lesson: 16K threads need huge per-thread MLP; ptxas gave regs=32 -> ~4
// loads in flight -> 1.3 TB/s. Fix: explicit double-buffered pipeline, 8
// timesteps per block, two statically-named buffer sets (A/B) so everything
// stays in registers. Steady state: 16 LDG.128 in flight per thread (~4 MB
// chip-wide) while the previous block's FMA chain executes.

#define NUM_NEURONS 65536
#define T_STEPS     1000
#define NVEC        (NUM_NEURONS / 4)     // 16384 float4 lanes
#define THREADS     64
#define BLOCKS      (NVEC / THREADS)      // 256
#define STAGES      8                     // timesteps per pipeline block

__device__ __forceinline__ float4 lif_step(const float4 i4, const float4 n4,
                                           float4& V, float4& th)
{
    const float decay = 0.05f, eta = 0.1f, nstd = 0.1f;
    const float thmin = 0.5f, thmax = 2.0f;
    float4 s;
#define LIF_C(c)                                                     \
    {                                                                \
        float ie = fmaf(nstd, n4.c, i4.c);                           \
        float v  = fmaf(decay, ie - V.c, V.c);                       \
        bool  sp = (v >= th.c);                                      \
        s.c  = sp ? 1.0f : 0.0f;                                     \
        V.c  = sp ? 0.0f : v;                                        \
        th.c = fminf(fmaxf(fmaf(eta, s.c, th.c), thmin), thmax);     \
    }
    LIF_C(x) LIF_C(y) LIF_C(z) LIF_C(w)
#undef LIF_C
    return s;
}

__global__ __launch_bounds__(THREADS)
void lif_kernel(const float4* __restrict__ icur,
                const float4* __restrict__ nz,
                float4* __restrict__ out)
{
    const int idx = blockIdx.x * THREADS + threadIdx.x;   // 0 .. NVEC-1

    const float4* ip = icur + idx;
    const float4* np = nz   + idx;
    float4*       op = out  + idx;

    float4 V  = make_float4(0.0f, 0.0f, 0.0f, 0.0f);
    float4 th = make_float4(1.0f, 1.0f, 1.0f, 1.0f);

    float4 AI[STAGES], AN[STAGES], BI[STAGES], BN[STAGES];

#define LOAD_BLK(BI_, BN_, tb)                                        \
    _Pragma("unroll")                                                 \
    for (int j = 0; j < STAGES; j++) {                                \
        BI_[j] = __ldcs(ip + (size_t)((tb) + j) * NVEC);              \
        BN_[j] = __ldcs(np + (size_t)((tb) + j) * NVEC);              \
    }

#define COMP_BLK(BI_, BN_, tb)                                        \
    _Pragma("unroll")                                                 \
    for (int j = 0; j < STAGES; j++) {                                \
        float4 s = lif_step(BI_[j], BN_[j], V, th);                   \
        __stcs(op + (size_t)((tb) + j) * NVEC, s);                    \
    }

    // 125 blocks of 8 timesteps: 62 A/B pairs + 1 epilogue block.
    LOAD_BLK(AI, AN, 0)

    for (int p = 0; p < 62; p++) {
        const int tb = p * 2 * STAGES;          // A-block start
        LOAD_BLK(BI, BN, tb + STAGES)           // prefetch B
        COMP_BLK(AI, AN, tb)                    // compute A (loads in flight)
        LOAD_BLK(AI, AN, tb + 2 * STAGES)       // prefetch next A (p=61 -> 992)
        COMP_BLK(BI, BN, tb + STAGES)           // compute B
    }

    COMP_BLK(AI, AN, T_STEPS - STAGES)          // t = 992..999

#undef LOAD_BLK
#undef COMP_BLK
}

extern "C" void kernel_launch(void* const* d_in, const int* in_sizes, int n_in,
                              void* d_out, int out_size)
{
    const float4* icur = (const float4*)d_in[0];   // input_current (T, N) f32
    const float4* nz   = (const float4*)d_in[1];   // noise         (T, N) f32
    float4*       out  = (float4*)d_out;           // spikes        (T, N) f32

    lif_kernel<<<BLOCKS, THREADS>>>(icur, nz, out);
}

// round 3
// speedup vs baseline: 4.0367x; 1.0565x over previous
#include <cuda_runtime.h>

// LIF neuron group, T=1000 serial steps x 65536 neurons. Pure HBM stream.
// R2: A/B register pipeline got DRAM to 63.8% @ 3.5 warps/SM — stall windows
// at each compute-block start are uncovered because the SM has too few
// independent warps. R3: float2 lanes -> 32768 threads (~7 warps/SM), same
// chip-wide in-flight bytes, 2x issue streams. STAGES=8 kept (125 blocks,
// odd -> prologue + 62 pairs + epilogue structure unchanged).

#define NUM_NEURONS 65536
#define T_STEPS     1000
#define NVEC        (NUM_NEURONS / 2)     // 32768 float2 lanes
#define THREADS     128
#define BLOCKS      (NVEC / THREADS)      // 256 blocks x 4 warps
#define STAGES      8                     // timesteps per pipeline block

__device__ __forceinline__ float2 lif_step(const float2 i2, const float2 n2,
                                           float2& V, float2& th)
{
    const float decay = 0.05f, eta = 0.1f, nstd = 0.1f;
    const float thmin = 0.5f, thmax = 2.0f;
    float2 s;
#define LIF_C(c)                                                     \
    {                                                                \
        float ie = fmaf(nstd, n2.c, i2.c);                           \
        float v  = fmaf(decay, ie - V.c, V.c);                       \
        bool  sp = (v >= th.c);                                      \
        s.c  = sp ? 1.0f : 0.0f;                                     \
        V.c  = sp ? 0.0f : v;                                        \
        th.c = fminf(fmaxf(fmaf(eta, s.c, th.c), thmin), thmax);     \
    }
    LIF_C(x) LIF_C(y)
#undef LIF_C
    return s;
}

__global__ __launch_bounds__(THREADS)
void lif_kernel(const float2* __restrict__ icur,
                const float2* __restrict__ nz,
                float2* __restrict__ out)
{
    const int idx = blockIdx.x * THREADS + threadIdx.x;   // 0 .. NVEC-1

    const float2* ip = icur + idx;
    const float2* np = nz   + idx;
    float2*       op = out  + idx;

    float2 V  = make_float2(0.0f, 0.0f);
    float2 th = make_float2(1.0f, 1.0f);

    float2 AI[STAGES], AN[STAGES], BI[STAGES], BN[STAGES];

#define LOAD_BLK(BI_, BN_, tb)                                        \
    _Pragma("unroll")                                                 \
    for (int j = 0; j < STAGES; j++) {                                \
        BI_[j] = __ldcs(ip + (size_t)((tb) + j) * NVEC);              \
        BN_[j] = __ldcs(np + (size_t)((tb) + j) * NVEC);              \
    }

#define COMP_BLK(BI_, BN_, tb)                                        \
    _Pragma("unroll")                                                 \
    for (int j = 0; j < STAGES; j++) {                                \
        float2 s = lif_step(BI_[j], BN_[j], V, th);                   \
        __stcs(op + (size_t)((tb) + j) * NVEC, s);                    \
    }

    // 125 blocks of 8 timesteps: prologue + 62 A/B pairs + 1 epilogue block.
    LOAD_BLK(AI, AN, 0)

    for (int p = 0; p < 62; p++) {
        const int tb = p * 2 * STAGES;          // A-block start
        LOAD_BLK(BI, BN, tb + STAGES)           // prefetch B
        COMP_BLK(AI, AN, tb)                    // compute A (B loads in flight)
        LOAD_BLK(AI, AN, tb + 2 * STAGES)       // prefetch next A (p=61 -> 992)
        COMP_BLK(BI, BN, tb + STAGES)           // compute B (A loads in flight)
    }

    COMP_BLK(AI, AN, T_STEPS - STAGES)          // t = 992..999

#undef LOAD_BLK
#undef COMP_BLK
}

extern "C" void kernel_launch(void* const* d_in, const int* in_sizes, int n_in,
                              void* d_out, int out_size)
{
    const float2* icur = (const float2*)d_in[0];   // input_current (T, N) f32
    const float2* nz   = (const float2*)d_in[1];   // noise         (T, N) f32
    float2*       out  = (float2*)d_out;           // spikes        (T, N) f32

    lif_kernel<<<BLOCKS, THREADS>>>(icur, nz, out);
}

// round 4
// speedup vs baseline: 4.5324x; 1.1228x over previous
#include <cuda_runtime.h>

// LIF neuron group, T=1000 serial steps x 65536 neurons. Pure HBM stream.
// R3 post-mortem: more warps didn't help (DRAM stuck ~66%). Two real issues:
//  (a) grid=256 on 148 SMs -> 108 SMs carry 2 blocks, 40 carry 1; the 40
//      finish early and the tail runs with too few in-flight bytes.
//      Fix: 1024 one-warp blocks -> 7-vs-6 per SM (1.2% imbalance).
//  (b) in-flight ~4 MB was marginal vs the latency-BW product. Fix: triple
//      buffer (load 2 blocks ahead) -> ~32 LDG.64 in flight/thread (~8.4 MB).

#define NUM_NEURONS 65536
#define T_STEPS     1000
#define NVEC        (NUM_NEURONS / 2)     // 32768 float2 lanes
#define THREADS     32                    // 1 warp per block
#define BLOCKS      (NVEC / THREADS)      // 1024 blocks -> 7 vs 6 per SM
#define STAGES      8                     // timesteps per pipeline block (125 blocks)

__device__ __forceinline__ float2 lif_step(const float2 i2, const float2 n2,
                                           float2& V, float2& th)
{
    const float decay = 0.05f, eta = 0.1f, nstd = 0.1f;
    const float thmin = 0.5f, thmax = 2.0f;
    float2 s;
#define LIF_C(c)                                                     \
    {                                                                \
        float ie = fmaf(nstd, n2.c, i2.c);                           \
        float v  = fmaf(decay, ie - V.c, V.c);                       \
        bool  sp = (v >= th.c);                                      \
        s.c  = sp ? 1.0f : 0.0f;                                     \
        V.c  = sp ? 0.0f : v;                                        \
        th.c = fminf(fmaxf(fmaf(eta, s.c, th.c), thmin), thmax);     \
    }
    LIF_C(x) LIF_C(y)
#undef LIF_C
    return s;
}

__global__ __launch_bounds__(THREADS)
void lif_kernel(const float2* __restrict__ icur,
                const float2* __restrict__ nz,
                float2* __restrict__ out)
{
    const int idx = blockIdx.x * THREADS + threadIdx.x;   // 0 .. NVEC-1

    const float2* ip = icur + idx;
    const float2* np = nz   + idx;
    float2*       op = out  + idx;

    float2 V  = make_float2(0.0f, 0.0f);
    float2 th = make_float2(1.0f, 1.0f);

    float2 AI[STAGES], AN[STAGES];
    float2 BI[STAGES], BN[STAGES];
    float2 CI[STAGES], CN[STAGES];

    // blk b covers timesteps [b*STAGES, (b+1)*STAGES)
#define LOAD_BLK(I_, N_, b)                                           \
    _Pragma("unroll")                                                 \
    for (int j = 0; j < STAGES; j++) {                                \
        I_[j] = __ldcs(ip + (size_t)((b) * STAGES + j) * NVEC);       \
        N_[j] = __ldcs(np + (size_t)((b) * STAGES + j) * NVEC);       \
    }

#define COMP_BLK(I_, N_, b)                                           \
    _Pragma("unroll")                                                 \
    for (int j = 0; j < STAGES; j++) {                                \
        float2 s = lif_step(I_[j], N_[j], V, th);                     \
        __stcs(op + (size_t)((b) * STAGES + j) * NVEC, s);            \
    }

    // 125 blocks of 8. Triple buffer: loads run 2 blocks ahead of compute.
    LOAD_BLK(AI, AN, 0)
    LOAD_BLK(BI, BN, 1)

    for (int p = 0; p < 41; p++) {
        const int b = 3 * p;
        LOAD_BLK(CI, CN, b + 2)   COMP_BLK(AI, AN, b)        // b+2 <= 122
        LOAD_BLK(AI, AN, b + 3)   COMP_BLK(BI, BN, b + 1)    // b+3 <= 123
        LOAD_BLK(BI, BN, b + 4)   COMP_BLK(CI, CN, b + 2)    // b+4 <= 124
    }
    // loop computed blocks 0..122; A holds 123, B holds 124
    COMP_BLK(AI, AN, 123)
    COMP_BLK(BI, BN, 124)

#undef LOAD_BLK
#undef COMP_BLK
}

extern "C" void kernel_launch(void* const* d_in, const int* in_sizes, int n_in,
                              void* d_out, int out_size)
{
    const float2* icur = (const float2*)d_in[0];   // input_current (T, N) f32
    const float2* nz   = (const float2*)d_in[1];   // noise         (T, N) f32
    float2*       out  = (float2*)d_out;           // spikes        (T, N) f32

    lif_kernel<<<BLOCKS, THREADS>>>(icur, nz, out);
}

// round 5
// speedup vs baseline: 5.0060x; 1.1045x over previous
#include <cuda_runtime.h>

// LIF neuron group, T=1000 serial steps x 65536 neurons. Pure HBM stream
// (512 MB read + 256 MB write). R2->R4: DRAM% tracks in-flight bytes
// monotonically (63.8 -> 66.8 -> 74.7). R4's regs=96 == raw buffer size =>
// ptxas compressed the triple buffer. R5: quad buffer (load 3 ahead,
// ~12 MB chip-wide in flight) + __launch_bounds__(32,7) to lift the reg cap
// to 255 so the pipeline stays live. Keep 1024 one-warp blocks (7-vs-6 per
// SM, 1.4% imbalance) and float2 lanes.

#define NUM_NEURONS 65536
#define T_STEPS     1000
#define NVEC        (NUM_NEURONS / 2)     // 32768 float2 lanes
#define THREADS     32                    // 1 warp per block
#define BLOCKS      (NVEC / THREADS)      // 1024 blocks
#define STAGES      8                     // timesteps per pipeline block (125 blocks)

__device__ __forceinline__ float2 lif_step(const float2 i2, const float2 n2,
                                           float2& V, float2& th)
{
    const float decay = 0.05f, eta = 0.1f, nstd = 0.1f;
    const float thmin = 0.5f, thmax = 2.0f;
    float2 s;
#define LIF_C(c)                                                     \
    {                                                                \
        float ie = fmaf(nstd, n2.c, i2.c);                           \
        float v  = fmaf(decay, ie - V.c, V.c);                       \
        bool  sp = (v >= th.c);                                      \
        s.c  = sp ? 1.0f : 0.0f;                                     \
        V.c  = sp ? 0.0f : v;                                        \
        th.c = fminf(fmaxf(fmaf(eta, s.c, th.c), thmin), thmax);     \
    }
    LIF_C(x) LIF_C(y)
#undef LIF_C
    return s;
}

__global__ __launch_bounds__(THREADS, 7)
void lif_kernel(const float2* __restrict__ icur,
                const float2* __restrict__ nz,
                float2* __restrict__ out)
{
    const int idx = blockIdx.x * THREADS + threadIdx.x;   // 0 .. NVEC-1

    const float2* ip = icur + idx;
    const float2* np = nz   + idx;
    float2*       op = out  + idx;

    float2 V  = make_float2(0.0f, 0.0f);
    float2 th = make_float2(1.0f, 1.0f);

    float2 AI[STAGES], AN[STAGES];
    float2 BI[STAGES], BN[STAGES];
    float2 CI[STAGES], CN[STAGES];
    float2 DI[STAGES], DN[STAGES];

    // blk b covers timesteps [b*STAGES, (b+1)*STAGES)
#define LOAD_BLK(I_, N_, b)                                           \
    _Pragma("unroll")                                                 \
    for (int j = 0; j < STAGES; j++) {                                \
        I_[j] = __ldcs(ip + (size_t)((b) * STAGES + j) * NVEC);       \
        N_[j] = __ldcs(np + (size_t)((b) * STAGES + j) * NVEC);       \
    }

#define COMP_BLK(I_, N_, b)                                           \
    _Pragma("unroll")                                                 \
    for (int j = 0; j < STAGES; j++) {                                \
        float2 s = lif_step(I_[j], N_[j], V, th);                     \
        __stcs(op + (size_t)((b) * STAGES + j) * NVEC, s);            \
    }

    // 125 blocks of 8. Quad buffer: loads run 3 blocks ahead of compute.
    LOAD_BLK(AI, AN, 0)
    LOAD_BLK(BI, BN, 1)
    LOAD_BLK(CI, CN, 2)

    for (int p = 0; p < 30; p++) {
        const int b = 4 * p;
        LOAD_BLK(DI, DN, b + 3)   COMP_BLK(AI, AN, b)        // load <= 119+3=122
        LOAD_BLK(AI, AN, b + 4)   COMP_BLK(BI, BN, b + 1)
        LOAD_BLK(BI, BN, b + 5)   COMP_BLK(CI, CN, b + 2)
        LOAD_BLK(CI, CN, b + 6)   COMP_BLK(DI, DN, b + 3)    // p=29: load 122, comp 119
    }
    // computed 0..119; A=120, B=121, C=122
    LOAD_BLK(DI, DN, 123)   COMP_BLK(AI, AN, 120)
    LOAD_BLK(AI, AN, 124)   COMP_BLK(BI, BN, 121)
    COMP_BLK(CI, CN, 122)
    COMP_BLK(DI, DN, 123)
    COMP_BLK(AI, AN, 124)

#undef LOAD_BLK
#undef COMP_BLK
}

extern "C" void kernel_launch(void* const* d_in, const int* in_sizes, int n_in,
                              void* d_out, int out_size)
{
    const float2* icur = (const float2*)d_in[0];   // input_current (T, N) f32
    const float2* nz   = (const float2*)d_in[1];   // noise         (T, N) f32
    float2*       out  = (float2*)d_out;           // spikes        (T, N) f32

    lif_kernel<<<BLOCKS, THREADS>>>(icur, nz, out);
}

// round 6
// speedup vs baseline: 5.0074x; 1.0003x over previous
#include <cuda_runtime.h>

// LIF neuron group, T=1000 serial steps x 65536 neurons. Pure HBM stream
// (512 MB read + 256 MB write; floor ~96us @ 8 TB/s spec).
// Validated model R2->R5: DRAM% tracks designed in-flight bytes
// (63.8 -> 66.8 -> 74.7 -> 82.7%). R6: quint buffer (load 4 blocks ahead),
// 512 B/thread in flight (~16.8 MB chip-wide). regs ~185 < 255 cap from
// __launch_bounds__(32,7). Keep 1024 one-warp blocks (7-vs-6 per SM),
// float2 lanes, .cs on loads+stores.

#define NUM_NEURONS 65536
#define T_STEPS     1000
#define NVEC        (NUM_NEURONS / 2)     // 32768 float2 lanes
#define THREADS     32                    // 1 warp per block
#define BLOCKS      (NVEC / THREADS)      // 1024 blocks
#define STAGES      8                     // timesteps per pipeline block (125 blocks)

__device__ __forceinline__ float2 lif_step(const float2 i2, const float2 n2,
                                           float2& V, float2& th)
{
    const float decay = 0.05f, eta = 0.1f, nstd = 0.1f;
    const float thmin = 0.5f, thmax = 2.0f;
    float2 s;
#define LIF_C(c)                                                     \
    {                                                                \
        float ie = fmaf(nstd, n2.c, i2.c);                           \
        float v  = fmaf(decay, ie - V.c, V.c);                       \
        bool  sp = (v >= th.c);                                      \
        s.c  = sp ? 1.0f : 0.0f;                                     \
        V.c  = sp ? 0.0f : v;                                        \
        th.c = fminf(fmaxf(fmaf(eta, s.c, th.c), thmin), thmax);     \
    }
    LIF_C(x) LIF_C(y)
#undef LIF_C
    return s;
}

__global__ __launch_bounds__(THREADS, 7)
void lif_kernel(const float2* __restrict__ icur,
                const float2* __restrict__ nz,
                float2* __restrict__ out)
{
    const int idx = blockIdx.x * THREADS + threadIdx.x;   // 0 .. NVEC-1

    const float2* ip = icur + idx;
    const float2* np = nz   + idx;
    float2*       op = out  + idx;

    float2 V  = make_float2(0.0f, 0.0f);
    float2 th = make_float2(1.0f, 1.0f);

    float2 AI[STAGES], AN[STAGES];
    float2 BI[STAGES], BN[STAGES];
    float2 CI[STAGES], CN[STAGES];
    float2 DI[STAGES], DN[STAGES];
    float2 EI[STAGES], EN[STAGES];

    // blk b covers timesteps [b*STAGES, (b+1)*STAGES)
#define LOAD_BLK(I_, N_, b)                                           \
    _Pragma("unroll")                                                 \
    for (int j = 0; j < STAGES; j++) {                                \
        I_[j] = __ldcs(ip + (size_t)((b) * STAGES + j) * NVEC);       \
        N_[j] = __ldcs(np + (size_t)((b) * STAGES + j) * NVEC);       \
    }

#define COMP_BLK(I_, N_, b)                                           \
    _Pragma("unroll")                                                 \
    for (int j = 0; j < STAGES; j++) {                                \
        float2 s = lif_step(I_[j], N_[j], V, th);                     \
        __stcs(op + (size_t)((b) * STAGES + j) * NVEC, s);            \
    }

    // 125 blocks of 8. Quint buffer: loads run 4 blocks ahead of compute.
    LOAD_BLK(AI, AN, 0)
    LOAD_BLK(BI, BN, 1)
    LOAD_BLK(CI, CN, 2)
    LOAD_BLK(DI, DN, 3)

    for (int p = 0; p < 24; p++) {
        const int b = 5 * p;                                 // 0,5,...,115
        LOAD_BLK(EI, EN, b + 4)   COMP_BLK(AI, AN, b)        // load <= 119
        LOAD_BLK(AI, AN, b + 5)   COMP_BLK(BI, BN, b + 1)    // load <= 120
        LOAD_BLK(BI, BN, b + 6)   COMP_BLK(CI, CN, b + 2)    // load <= 121
        LOAD_BLK(CI, CN, b + 7)   COMP_BLK(DI, DN, b + 3)    // load <= 122
        LOAD_BLK(DI, DN, b + 8)   COMP_BLK(EI, EN, b + 4)    // load <= 123
    }
    // computed 0..119; A=120, B=121, C=122, D=123
    LOAD_BLK(EI, EN, 124)   COMP_BLK(AI, AN, 120)
    COMP_BLK(BI, BN, 121)
    COMP_BLK(CI, CN, 122)
    COMP_BLK(DI, DN, 123)
    COMP_BLK(EI, EN, 124)

#undef LOAD_BLK
#undef COMP_BLK
}

extern "C" void kernel_launch(void* const* d_in, const int* in_sizes, int n_in,
                              void* d_out, int out_size)
{
    const float2* icur = (const float2*)d_in[0];   // input_current (T, N) f32
    const float2* nz   = (const float2*)d_in[1];   // noise         (T, N) f32
    float2*       out  = (float2*)d_out;           // spikes        (T, N) f32

    lif_kernel<<<BLOCKS, THREADS>>>(icur, nz, out);
}